// round 7
// baseline (speedup 1.0000x reference)
#include <cuda_runtime.h>
#include <math.h>

#define BB 16
#define CC 64
#define NN 4096
#define KK 128
#define MM 257
#define TEMBD 256
#define HH 128
#define MP 288
#define NSPLIT 8
#define PI_F 3.14159265358979323846f

typedef unsigned long long ull_t;

__device__ __forceinline__ ull_t f2fma(ull_t a, ull_t b, ull_t c){
    ull_t d; asm("fma.rn.f32x2 %0, %1, %2, %3;" : "=l"(d) : "l"(a), "l"(b), "l"(c)); return d;
}
__device__ __forceinline__ ull_t f2add(ull_t a, ull_t b){
    ull_t d; asm("add.rn.f32x2 %0, %1, %2;" : "=l"(d) : "l"(a), "l"(b)); return d;
}
__device__ __forceinline__ ull_t f2dup(float x){
    ull_t d; asm("mov.b64 %0, {%1, %1};" : "=l"(d) : "f"(x)); return d;
}
__device__ __forceinline__ float2 f2unpack(ull_t v){
    float lo, hi; asm("mov.b64 {%0, %1}, %2;" : "=f"(lo), "=f"(hi) : "l"(v));
    return make_float2(lo, hi);
}

// ---------------- device scratch ----------------
__device__ float g_tau[BB];
__device__ float g_gate[BB*MM];
__device__ float g_tvec[BB*CC];
__device__ int   g_midx[MP];
__device__ int   g_Mact;
__device__ float g_kcpt[MP];
__device__ float g_ccpt[MP];
__device__ float g_iwcpt[MP];
__device__ float g_Xr[(size_t)NSPLIT*BB*CC*MP];
__device__ float g_Xi[(size_t)NSPLIT*BB*CC*MP];
__device__ float g_Yr[(size_t)BB*CC*MP];
__device__ float g_Yi[(size_t)BB*CC*MP];   // stored NEGATED

__device__ __forceinline__ float sigmoidf_(float x){ return 1.f/(1.f+expf(-x)); }
__device__ __forceinline__ float softplusf_(float x){ return log1pf(expf(x)); }

// ---------------- kernel A: per-batch MLP tau + tproj vec (16 blocks) ----------------
__global__ void __launch_bounds__(256) k_batch(const float* __restrict__ temb,
                                               const float* __restrict__ tproj_w,
                                               const float* __restrict__ tproj_b,
                                               const float* __restrict__ mlp_w1,
                                               const float* __restrict__ mlp_b1,
                                               const float* __restrict__ mlp_w2,
                                               const float* __restrict__ mlp_b2,
                                               const float* __restrict__ tau0p,
                                               const float* __restrict__ tau1p)
{
    int b = blockIdx.x;
    int tid = threadIdx.x;
    __shared__ float te[TEMBD], si[TEMBD];
    __shared__ float hid[HH];
    float v = temb[b*TEMBD + tid];
    te[tid] = v;
    si[tid] = v * sigmoidf_(v);
    __syncthreads();
    if (tid < HH) {
        float acc = mlp_b1[tid];
        const float* w = mlp_w1 + tid*TEMBD;
        #pragma unroll 8
        for (int t = 0; t < TEMBD; t++) acc = fmaf(te[t], w[t], acc);
        hid[tid] = acc * sigmoidf_(acc);
    } else if (tid < HH + CC) {
        int c = tid - HH;
        float acc = tproj_b[c];
        const float* w = tproj_w + c*TEMBD;
        #pragma unroll 8
        for (int t = 0; t < TEMBD; t++) acc = fmaf(si[t], w[t], acc);
        g_tvec[b*CC + c] = acc;
    }
    __syncthreads();
    if (tid == 0) {
        float acc = mlp_b2[0];
        for (int h = 0; h < HH; h++) acc = fmaf(hid[h], mlp_w2[h], acc);
        g_tau[b] = tau0p[0] + softplusf_(tau1p[0]) * tanhf(acc);
    }
}

// ---------------- kernel B: kappa, gates, compaction (1 block) ----------------
__global__ void __launch_bounds__(256) k_kappa(const float* __restrict__ kappa_raw,
                                               const float* __restrict__ gabor_c,
                                               const float* __restrict__ gabor_omega_raw,
                                               const float* __restrict__ alphap,
                                               const float* __restrict__ glowp,
                                               const float* __restrict__ gmidp,
                                               const float* __restrict__ ghighp)
{
    __shared__ float kpos[KK];
    __shared__ float kap[MM];
    __shared__ float gmax[MM];
    __shared__ float tau[BB];
    __shared__ float th1s, th2s;
    int tid = threadIdx.x;

    if (tid < KK) kpos[tid] = softplusf_(kappa_raw[tid]);
    if (tid < BB) tau[tid] = g_tau[tid];
    __syncthreads();
    if (tid == 0) {
        float s = 0.f;
        for (int k = 0; k < KK; k++) { s += kpos[k]; kpos[k] = s; }
        // sorted |kappa| = [0, kpos0,kpos0, kpos1,kpos1, ...], 257 values
        th1s = kpos[50]  + 0.4f*(kpos[51] - kpos[50]);
        th2s = kpos[101] + 0.8f*(kpos[102] - kpos[101]);
    }
    __syncthreads();

    float alpha = softplusf_(alphap[0]) + 1e-12f;
    float gl = sigmoidf_(glowp[0]);
    float gm = sigmoidf_(gmidp[0]);
    float gh = sigmoidf_(ghighp[0]);
    for (int m = tid; m < MM; m += blockDim.x) {
        float kv = (m < KK) ? -kpos[KK-1-m] : ((m == KK) ? 0.f : kpos[m-KK-1]);
        kap[m] = kv;
        float ka = fabsf(kv);
        float bandv = (ka <= th1s) ? gl : ((ka <= th2s) ? gm : gh);
        float mx = 0.f;
        for (int b = 0; b < BB; b++) {
            float g = bandv * sigmoidf_(alpha*(tau[b]-ka));
            g_gate[b*MM+m] = g;
            mx = fmaxf(mx, g);
        }
        gmax[m] = mx;
    }
    __syncthreads();

    if (tid == 0) {
        int cnt = 0;
        for (int m = 0; m < MM; m++) {
            if (gmax[m] > 1e-7f) {
                g_midx[cnt]  = m;
                g_kcpt[cnt]  = kap[m];
                g_ccpt[cnt]  = gabor_c[m];
                float om = fmaxf(softplusf_(gabor_omega_raw[m]), 1e-6f);
                g_iwcpt[cnt] = 1.f/om;
                cnt++;
            }
        }
        g_Mact = cnt;
        for (int j = cnt; j < MP; j++) { g_kcpt[j]=0.f; g_ccpt[j]=0.f; g_iwcpt[j]=1.f; g_midx[j]=0; }
    }
}

// ---------------- kernel 1: analysis (f32x2 GEMM, conflict-free smem) ----------------
// block: 32 modes x 512 n x 64 c; two n-halves of 128 threads; thread tile 4c x 4m
__global__ void __launch_bounds__(256) k_analysis(const float* __restrict__ x_feat,
                                                  const float* __restrict__ z)
{
    int mt = blockIdx.x, ns = blockIdx.y, b = blockIdx.z;
    int Mact = g_Mact;
    int m0 = mt*32;
    if (m0 >= Mact) return;

    __shared__ float km[32], cm[32], iw[32];
    __shared__ float basis[2][64][32];      // [0]=cos*w, [1]=sin*w; also reused as merge stage
    __shared__ ull_t xsm2[64][66];          // dup-packed x, pad 66 for 16B-aligned pair reads

    int tid = threadIdx.x;
    if (tid < 32){ km[tid]=g_kcpt[m0+tid]; cm[tid]=g_ccpt[m0+tid]; iw[tid]=g_iwcpt[m0+tid]; }
    int half = tid >> 7;
    int mg = tid & 7;
    int cg = (tid >> 3) & 15;
    int c_tid = tid & 63, q_tid = tid >> 6;
    float tvc = g_tvec[b*CC + c_tid];
    const float* zb = z + b*NN;

    ull_t arp[4][2], aip[4][2];
    #pragma unroll
    for (int a=0;a<4;a++){ arp[a][0]=0ull; arp[a][1]=0ull; aip[a][0]=0ull; aip[a][1]=0ull; }

    for (int ch = 0; ch < 8; ch++){
        int n0 = ns*512 + ch*64;
        __syncthreads();
        {
            const float4* xg = (const float4*)(x_feat + ((size_t)(b*CC + c_tid))*NN + n0);
            #pragma unroll
            for (int q=0;q<4;q++){
                float4 v = xg[q_tid*4+q];
                int nn = q_tid*16 + q*4;
                xsm2[nn+0][c_tid] = f2dup(v.x+tvc);
                xsm2[nn+1][c_tid] = f2dup(v.y+tvc);
                xsm2[nn+2][c_tid] = f2dup(v.z+tvc);
                xsm2[nn+3][c_tid] = f2dup(v.w+tvc);
            }
        }
        #pragma unroll
        for (int e=0;e<8;e++){
            int idx = e*256 + tid;
            int nn = idx >> 5, mm = idx & 31;
            float zv = __ldg(zb + n0 + nn);
            float s,c; __sincosf(zv*km[mm], &s, &c);
            float d = (zv*(1.f/PI_F) - cm[mm])*iw[mm];
            float w = __expf(-0.5f*d*d);
            basis[0][nn][mm] = c*w;
            basis[1][nn][mm] = s*w;
        }
        __syncthreads();
        int nb = half*32;
        #pragma unroll 4
        for (int n2=0;n2<32;n2++){
            int nn = nb + n2;
            ulonglong2 x01 = *(const ulonglong2*)&xsm2[nn][cg*4];
            ulonglong2 x23 = *(const ulonglong2*)&xsm2[nn][cg*4+2];
            ulonglong2 cp  = *(const ulonglong2*)&basis[0][nn][mg*4];
            ulonglong2 sp  = *(const ulonglong2*)&basis[1][nn][mg*4];
            ull_t xa[4] = {x01.x, x01.y, x23.x, x23.y};
            #pragma unroll
            for (int a=0;a<4;a++){
                arp[a][0] = f2fma(xa[a], cp.x, arp[a][0]);
                arp[a][1] = f2fma(xa[a], cp.y, arp[a][1]);
                aip[a][0] = f2fma(xa[a], sp.x, aip[a][0]);
                aip[a][1] = f2fma(xa[a], sp.y, aip[a][1]);
            }
        }
    }

    // merge the two n-halves via stride-1 (conflict-free) smem stage overlaid on basis
    ull_t* st = (ull_t*)&basis[0][0][0];   // 2048 ull = 16KB, exactly the basis arrays
    __syncthreads();
    if (half == 1){
        int t = tid - 128;
        #pragma unroll
        for (int a=0;a<4;a++){
            st[t + (a*2+0)*128]     = arp[a][0];
            st[t + (a*2+1)*128]     = arp[a][1];
            st[t + (8+a*2+0)*128]   = aip[a][0];
            st[t + (8+a*2+1)*128]   = aip[a][1];
        }
    }
    __syncthreads();
    if (half == 0){
        #pragma unroll
        for (int a=0;a<4;a++){
            arp[a][0] = f2add(arp[a][0], st[tid + (a*2+0)*128]);
            arp[a][1] = f2add(arp[a][1], st[tid + (a*2+1)*128]);
            aip[a][0] = f2add(aip[a][0], st[tid + (8+a*2+0)*128]);
            aip[a][1] = f2add(aip[a][1], st[tid + (8+a*2+1)*128]);
        }
        size_t base = ((size_t)(ns*BB + b)*CC + cg*4)*MP + m0 + mg*4;
        #pragma unroll
        for (int a=0;a<4;a++){
            float2 r0 = f2unpack(arp[a][0]), r1 = f2unpack(arp[a][1]);
            float2 i0 = f2unpack(aip[a][0]), i1 = f2unpack(aip[a][1]);
            float4 r; r.x=r0.x; r.y=r0.y; r.z=r1.x; r.w=r1.y;
            float4 i; i.x=i0.x; i.y=i0.y; i.z=i1.x; i.w=i1.y;
            *(float4*)&g_Xr[base + (size_t)a*MP] = r;
            *(float4*)&g_Xi[base + (size_t)a*MP] = i;
        }
    }
}

// ---------------- kernel 2: combine splits, gate, complex weight (Yi negated) ----------------
__global__ void k_comb(const float* __restrict__ wr, const float* __restrict__ wi)
{
    int bc = blockIdx.x;
    int b = bc / CC, c = bc % CC;
    int j = threadIdx.x;
    size_t o = ((size_t)b*CC + c)*MP + j;
    if (j >= g_Mact) { g_Yr[o] = 0.f; g_Yi[o] = 0.f; return; }
    int m = g_midx[j];
    float xr = 0.f, xi = 0.f;
    #pragma unroll
    for (int ns = 0; ns < NSPLIT; ns++) {
        size_t idx = ((size_t)(ns*BB + b)*CC + c)*MP + j;
        xr += g_Xr[idx];
        xi += g_Xi[idx];
    }
    xr *=  (1.f/(float)NN);
    xi *= -(1.f/(float)NN);
    float g = g_gate[b*MM+m];
    float wrv = wr[c*MM+m], wiv = wi[c*MM+m];
    g_Yr[o] =  g*(xr*wrv - xi*wiv);
    g_Yi[o] = -g*(xr*wiv + xi*wrv);    // pre-negated for synthesis fma2
}

// ---------------- kernel 3: synthesis (f32x2 GEMM, conflict-free smem) ----------------
// block: 128 n x 64 c; warp = 8 channels, lane = 4 consecutive n; j-tiles of 16
__global__ void __launch_bounds__(256) k_synth(const float* __restrict__ z,
                                               const float* __restrict__ bias,
                                               float* __restrict__ out)
{
    int nt = blockIdx.x, b = blockIdx.y;
    int n0 = nt*128;
    __shared__ float zs[128], zp[128];
    __shared__ float kk[MP], cc2[MP], ii[MP];
    __shared__ float cw[16][128], sw[16][128];
    __shared__ ull_t y2r[16][65], y2i[16][65];   // dup-packed (Yi negated), pad 65

    int tid = threadIdx.x;
    if (tid < 128){
        float zv = z[b*NN + n0 + tid];
        zs[tid] = zv;
        zp[tid] = zv*(1.f/PI_F);
    }
    for (int j = tid; j < MP; j += 256){ kk[j]=g_kcpt[j]; cc2[j]=g_ccpt[j]; ii[j]=g_iwcpt[j]; }

    int w = tid >> 5, l = tid & 31;
    int cb = w*8, n4 = l*4;
    ull_t accp[8][2];
    #pragma unroll
    for (int c=0;c<8;c++){ accp[c][0]=0ull; accp[c][1]=0ull; }

    int Mact = g_Mact;
    int T = (Mact + 15) >> 4;
    int cl = tid >> 2, ql = tid & 3;
    size_t ybase = ((size_t)b*CC + cl)*MP;

    for (int t=0;t<T;t++){
        int j0 = t*16;
        __syncthreads();
        {
            float4 vr = *(const float4*)&g_Yr[ybase + j0 + ql*4];
            float4 vi = *(const float4*)&g_Yi[ybase + j0 + ql*4];
            y2r[ql*4+0][cl]=f2dup(vr.x); y2r[ql*4+1][cl]=f2dup(vr.y);
            y2r[ql*4+2][cl]=f2dup(vr.z); y2r[ql*4+3][cl]=f2dup(vr.w);
            y2i[ql*4+0][cl]=f2dup(vi.x); y2i[ql*4+1][cl]=f2dup(vi.y);
            y2i[ql*4+2][cl]=f2dup(vi.z); y2i[ql*4+3][cl]=f2dup(vi.w);
        }
        #pragma unroll
        for (int e=0;e<8;e++){
            int idx = e*256 + tid;
            int jj = idx >> 7, nb = idx & 127;
            float s,c; __sincosf(zs[nb]*kk[j0+jj], &s, &c);
            float d = (zp[nb]-cc2[j0+jj])*ii[j0+jj];
            float wgt = __expf(-0.5f*d*d);
            cw[jj][nb] = c*wgt;
            sw[jj][nb] = s*wgt;
        }
        __syncthreads();
        #pragma unroll 2
        for (int jj=0;jj<16;jj++){
            ulonglong2 cp = *(const ulonglong2*)&cw[jj][n4];
            ulonglong2 sp = *(const ulonglong2*)&sw[jj][n4];
            #pragma unroll
            for (int c=0;c<8;c++){
                ull_t yr = y2r[jj][cb+c];
                ull_t yi = y2i[jj][cb+c];
                accp[c][0] = f2fma(yr, cp.x, f2fma(yi, sp.x, accp[c][0]));
                accp[c][1] = f2fma(yr, cp.y, f2fma(yi, sp.y, accp[c][1]));
            }
        }
    }

    #pragma unroll
    for (int c=0;c<8;c++){
        int cc_ = cb + c;
        float bv = bias[cc_];
        float2 p0 = f2unpack(accp[c][0]), p1 = f2unpack(accp[c][1]);
        float4 o; o.x=p0.x+bv; o.y=p0.y+bv; o.z=p1.x+bv; o.w=p1.y+bv;
        *(float4*)(out + ((size_t)(b*CC + cc_))*NN + n0 + n4) = o;
    }
}

// ---------------- launch ----------------
extern "C" void kernel_launch(void* const* d_in, const int* in_sizes, int n_in,
                              void* d_out, int out_size)
{
    const float* x_feat          = (const float*)d_in[0];
    const float* z               = (const float*)d_in[1];
    const float* temb            = (const float*)d_in[2];
    const float* kappa_raw       = (const float*)d_in[3];
    const float* gabor_c         = (const float*)d_in[4];
    const float* gabor_omega_raw = (const float*)d_in[5];
    const float* wr              = (const float*)d_in[6];
    const float* wi              = (const float*)d_in[7];
    const float* bias            = (const float*)d_in[8];
    const float* tproj_w         = (const float*)d_in[9];
    const float* tproj_b         = (const float*)d_in[10];
    const float* mlp_w1          = (const float*)d_in[11];
    const float* mlp_b1          = (const float*)d_in[12];
    const float* mlp_w2          = (const float*)d_in[13];
    const float* mlp_b2          = (const float*)d_in[14];
    const float* tau0            = (const float*)d_in[15];
    const float* tau1            = (const float*)d_in[16];
    const float* alphar          = (const float*)d_in[17];
    const float* glow            = (const float*)d_in[18];
    const float* gmid            = (const float*)d_in[19];
    const float* ghigh           = (const float*)d_in[20];
    float* out = (float*)d_out;

    k_batch<<<BB, 256>>>(temb, tproj_w, tproj_b, mlp_w1, mlp_b1, mlp_w2, mlp_b2, tau0, tau1);
    k_kappa<<<1, 256>>>(kappa_raw, gabor_c, gabor_omega_raw, alphar, glow, gmid, ghigh);
    dim3 g1((MM + 31)/32, NSPLIT, BB);     // (9, 8, 16); inactive m-tiles early-exit
    k_analysis<<<g1, 256>>>(x_feat, z);
    k_comb<<<BB*CC, MP>>>(wr, wi);
    dim3 g2(NN/128, BB);                   // (32, 16)
    k_synth<<<g2, 256>>>(z, bias, out);
}

// round 10
// speedup vs baseline: 1.1944x; 1.1944x over previous
#include <cuda_runtime.h>
#include <math.h>

#define BB 16
#define CC 64
#define NN 4096
#define KK 128
#define MM 257
#define TEMBD 256
#define HH 128
#define MP 288
#define NSPLIT 16
#define PI_F 3.14159265358979323846f

typedef unsigned long long ull_t;

__device__ __forceinline__ ull_t f2fma(ull_t a, ull_t b, ull_t c){
    ull_t d; asm("fma.rn.f32x2 %0, %1, %2, %3;" : "=l"(d) : "l"(a), "l"(b), "l"(c)); return d;
}
__device__ __forceinline__ ull_t f2add(ull_t a, ull_t b){
    ull_t d; asm("add.rn.f32x2 %0, %1, %2;" : "=l"(d) : "l"(a), "l"(b)); return d;
}
__device__ __forceinline__ ull_t f2dup(float x){
    ull_t d; asm("mov.b64 %0, {%1, %1};" : "=l"(d) : "f"(x)); return d;
}
__device__ __forceinline__ float2 f2unpack(ull_t v){
    float lo, hi; asm("mov.b64 {%0, %1}, %2;" : "=f"(lo), "=f"(hi) : "l"(v));
    return make_float2(lo, hi);
}

// ---------------- device scratch ----------------
__device__ float g_tau[BB];
__device__ float g_gate[BB*MM];
__device__ float g_tvec[BB*CC];
__device__ int   g_midx[MP];
__device__ int   g_Mact;
__device__ float g_kcpt[MP];
__device__ float g_ccpt[MP];
__device__ float g_iwcpt[MP];
__device__ float g_Xr[(size_t)NSPLIT*BB*CC*MP];
__device__ float g_Xi[(size_t)NSPLIT*BB*CC*MP];
__device__ float g_Yr[(size_t)BB*CC*MP];
__device__ float g_Yi[(size_t)BB*CC*MP];   // stored NEGATED

__device__ __forceinline__ float sigmoidf_(float x){ return 1.f/(1.f+expf(-x)); }
__device__ __forceinline__ float softplusf_(float x){ return log1pf(expf(x)); }

// ---------------- dummy: shifts k_analysis to profiler slot #4 ----------------
__global__ void k_dummy() {}

// ---------------- kernel A: per-batch MLP tau + tproj vec (16 blocks) ----------------
__global__ void __launch_bounds__(256) k_batch(const float* __restrict__ temb,
                                               const float* __restrict__ tproj_w,
                                               const float* __restrict__ tproj_b,
                                               const float* __restrict__ mlp_w1,
                                               const float* __restrict__ mlp_b1,
                                               const float* __restrict__ mlp_w2,
                                               const float* __restrict__ mlp_b2,
                                               const float* __restrict__ tau0p,
                                               const float* __restrict__ tau1p)
{
    int b = blockIdx.x;
    int tid = threadIdx.x;
    __shared__ float te[TEMBD], si[TEMBD];
    __shared__ float hid[HH];
    float v = temb[b*TEMBD + tid];
    te[tid] = v;
    si[tid] = v * sigmoidf_(v);
    __syncthreads();
    if (tid < HH) {
        float acc = mlp_b1[tid];
        const float* w = mlp_w1 + tid*TEMBD;
        #pragma unroll 8
        for (int t = 0; t < TEMBD; t++) acc = fmaf(te[t], w[t], acc);
        hid[tid] = acc * sigmoidf_(acc);
    } else if (tid < HH + CC) {
        int c = tid - HH;
        float acc = tproj_b[c];
        const float* w = tproj_w + c*TEMBD;
        #pragma unroll 8
        for (int t = 0; t < TEMBD; t++) acc = fmaf(si[t], w[t], acc);
        g_tvec[b*CC + c] = acc;
    }
    __syncthreads();
    if (tid == 0) {
        float acc = mlp_b2[0];
        for (int h = 0; h < HH; h++) acc = fmaf(hid[h], mlp_w2[h], acc);
        g_tau[b] = tau0p[0] + softplusf_(tau1p[0]) * tanhf(acc);
    }
}

// ---------------- kernel B: kappa, gates, compaction (1 block) ----------------
__global__ void __launch_bounds__(256) k_kappa(const float* __restrict__ kappa_raw,
                                               const float* __restrict__ gabor_c,
                                               const float* __restrict__ gabor_omega_raw,
                                               const float* __restrict__ alphap,
                                               const float* __restrict__ glowp,
                                               const float* __restrict__ gmidp,
                                               const float* __restrict__ ghighp)
{
    __shared__ float kpos[KK];
    __shared__ float kap[MM];
    __shared__ float gmax[MM];
    __shared__ float tau[BB];
    __shared__ float th1s, th2s;
    int tid = threadIdx.x;

    if (tid < KK) kpos[tid] = softplusf_(kappa_raw[tid]);
    if (tid < BB) tau[tid] = g_tau[tid];
    __syncthreads();
    if (tid == 0) {
        float s = 0.f;
        for (int k = 0; k < KK; k++) { s += kpos[k]; kpos[k] = s; }
        th1s = kpos[50]  + 0.4f*(kpos[51] - kpos[50]);
        th2s = kpos[101] + 0.8f*(kpos[102] - kpos[101]);
    }
    __syncthreads();

    float alpha = softplusf_(alphap[0]) + 1e-12f;
    float gl = sigmoidf_(glowp[0]);
    float gm = sigmoidf_(gmidp[0]);
    float gh = sigmoidf_(ghighp[0]);
    for (int m = tid; m < MM; m += blockDim.x) {
        float kv = (m < KK) ? -kpos[KK-1-m] : ((m == KK) ? 0.f : kpos[m-KK-1]);
        kap[m] = kv;
        float ka = fabsf(kv);
        float bandv = (ka <= th1s) ? gl : ((ka <= th2s) ? gm : gh);
        float mx = 0.f;
        for (int b = 0; b < BB; b++) {
            float g = bandv * sigmoidf_(alpha*(tau[b]-ka));
            g_gate[b*MM+m] = g;
            mx = fmaxf(mx, g);
        }
        gmax[m] = mx;
    }
    __syncthreads();

    if (tid == 0) {
        int cnt = 0;
        for (int m = 0; m < MM; m++) {
            if (gmax[m] > 1e-7f) {
                g_midx[cnt]  = m;
                g_kcpt[cnt]  = kap[m];
                g_ccpt[cnt]  = gabor_c[m];
                float om = fmaxf(softplusf_(gabor_omega_raw[m]), 1e-6f);
                g_iwcpt[cnt] = 1.f/om;
                cnt++;
            }
        }
        g_Mact = cnt;
        for (int j = cnt; j < MP; j++) { g_kcpt[j]=0.f; g_ccpt[j]=0.f; g_iwcpt[j]=1.f; g_midx[j]=0; }
    }
}

// ---------------- kernel 1: analysis (64-wide m tile, 4c x 8m threads) ----------------
__global__ void __launch_bounds__(256) k_analysis(const float* __restrict__ x_feat,
                                                  const float* __restrict__ z)
{
    int mt = blockIdx.x, ns = blockIdx.y, b = blockIdx.z;
    int Mact = g_Mact;
    int m0 = mt*64;
    if (m0 >= Mact) return;

    __shared__ float km[64], cm[64], iw[64];
    __shared__ __align__(16) float xs[64][68];       // [n][c]
    __shared__ __align__(16) float cw[64][68];       // [n][m] cos*win
    __shared__ __align__(16) float sw[64][68];       // [n][m] sin*win

    int tid = threadIdx.x;
    if (tid < 64){ km[tid]=g_kcpt[m0+tid]; cm[tid]=g_ccpt[m0+tid]; iw[tid]=g_iwcpt[m0+tid]; }

    int pos  = tid & 127;
    int ngrp = tid >> 7;            // two 128-thread n-groups
    int cg = pos & 15;              // 16 c-groups x 4 channels
    int mg = pos >> 4;              // 8 m-groups x 8 modes (4 f2-pairs)
    int c_tid = tid & 63, q_tid = tid >> 6;   // x loader: 64 c x 4 n-quarters
    float tvc = g_tvec[b*CC + c_tid];
    const float* zb = z + b*NN;

    ull_t ar[4][4], ai[4][4];       // [c][m-pair]
    #pragma unroll
    for (int a=0;a<4;a++)
        #pragma unroll
        for (int k=0;k<4;k++){ ar[a][k]=0ull; ai[a][k]=0ull; }

    for (int ch = 0; ch < 4; ch++){
        int n0 = ns*256 + ch*64;
        __syncthreads();
        {   // x -> smem [n][c]
            const float4* xg = (const float4*)(x_feat + ((size_t)(b*CC + c_tid))*NN + n0);
            #pragma unroll
            for (int q=0;q<4;q++){
                float4 v = xg[q_tid*4+q];
                int nn = q_tid*16 + q*4;
                xs[nn+0][c_tid]=v.x+tvc; xs[nn+1][c_tid]=v.y+tvc;
                xs[nn+2][c_tid]=v.z+tvc; xs[nn+3][c_tid]=v.w+tvc;
            }
        }
        #pragma unroll
        for (int e=0;e<16;e++){    // basis: 64n x 64m
            int idx = e*256 + tid;
            int nn = idx >> 6, mm = idx & 63;
            float zv = __ldg(zb + n0 + nn);
            float s,c; __sincosf(zv*km[mm], &s, &c);
            float d = (zv*(1.f/PI_F) - cm[mm])*iw[mm];
            float w = __expf(-0.5f*d*d);
            cw[nn][mm] = c*w;
            sw[nn][mm] = s*w;
        }
        __syncthreads();
        int nb = ngrp*32;
        #pragma unroll 2
        for (int n2=0;n2<32;n2++){
            int nn = nb + n2;
            float4 xv = *(const float4*)&xs[nn][cg*4];
            ulonglong2 c01 = *(const ulonglong2*)&cw[nn][mg*8];
            ulonglong2 c23 = *(const ulonglong2*)&cw[nn][mg*8+4];
            ulonglong2 s01 = *(const ulonglong2*)&sw[nn][mg*8];
            ulonglong2 s23 = *(const ulonglong2*)&sw[nn][mg*8+4];
            ull_t cp[4] = {c01.x, c01.y, c23.x, c23.y};
            ull_t sp[4] = {s01.x, s01.y, s23.x, s23.y};
            ull_t xd[4] = {f2dup(xv.x), f2dup(xv.y), f2dup(xv.z), f2dup(xv.w)};
            #pragma unroll
            for (int a=0;a<4;a++)
                #pragma unroll
                for (int k=0;k<4;k++){
                    ar[a][k] = f2fma(xd[a], cp[k], ar[a][k]);
                    ai[a][k] = f2fma(xd[a], sp[k], ai[a][k]);
                }
        }
    }

    // two-round merge of n-groups through cw (interleaved, conflict-free)
    ull_t* st = (ull_t*)&cw[0][0];   // 64*68 floats = 2176 ull-slots >= 2048 needed
    __syncthreads();
    if (ngrp == 1){
        int t = tid - 128;
        #pragma unroll
        for (int a=0;a<4;a++)
            #pragma unroll
            for (int k=0;k<4;k++) st[(a*4+k)*128 + t] = ar[a][k];
    }
    __syncthreads();
    if (ngrp == 0){
        #pragma unroll
        for (int a=0;a<4;a++)
            #pragma unroll
            for (int k=0;k<4;k++) ar[a][k] = f2add(ar[a][k], st[(a*4+k)*128 + tid]);
    }
    __syncthreads();
    if (ngrp == 1){
        int t = tid - 128;
        #pragma unroll
        for (int a=0;a<4;a++)
            #pragma unroll
            for (int k=0;k<4;k++) st[(a*4+k)*128 + t] = ai[a][k];
    }
    __syncthreads();
    if (ngrp == 0){
        #pragma unroll
        for (int a=0;a<4;a++)
            #pragma unroll
            for (int k=0;k<4;k++) ai[a][k] = f2add(ai[a][k], st[(a*4+k)*128 + tid]);
        size_t base = ((size_t)(ns*BB + b)*CC + cg*4)*MP + m0 + mg*8;
        #pragma unroll
        for (int a=0;a<4;a++){
            float2 r0=f2unpack(ar[a][0]), r1=f2unpack(ar[a][1]), r2=f2unpack(ar[a][2]), r3=f2unpack(ar[a][3]);
            float2 i0=f2unpack(ai[a][0]), i1=f2unpack(ai[a][1]), i2=f2unpack(ai[a][2]), i3=f2unpack(ai[a][3]);
            float4 ra; ra.x=r0.x; ra.y=r0.y; ra.z=r1.x; ra.w=r1.y;
            float4 rb; rb.x=r2.x; rb.y=r2.y; rb.z=r3.x; rb.w=r3.y;
            float4 ia; ia.x=i0.x; ia.y=i0.y; ia.z=i1.x; ia.w=i1.y;
            float4 ib; ib.x=i2.x; ib.y=i2.y; ib.z=i3.x; ib.w=i3.y;
            float* pr = &g_Xr[base + (size_t)a*MP];
            float* pi = &g_Xi[base + (size_t)a*MP];
            *(float4*)pr = ra; *(float4*)(pr+4) = rb;
            *(float4*)pi = ia; *(float4*)(pi+4) = ib;
        }
    }
}

// ---------------- kernel 2: combine splits, gate, complex weight (Yi negated) ----------------
__global__ void k_comb(const float* __restrict__ wr, const float* __restrict__ wi)
{
    int bc = blockIdx.x;
    int b = bc / CC, c = bc % CC;
    int j = threadIdx.x;
    size_t o = ((size_t)b*CC + c)*MP + j;
    if (j >= g_Mact) { g_Yr[o] = 0.f; g_Yi[o] = 0.f; return; }
    int m = g_midx[j];
    float xr = 0.f, xi = 0.f;
    #pragma unroll
    for (int ns = 0; ns < NSPLIT; ns++) {
        size_t idx = ((size_t)(ns*BB + b)*CC + c)*MP + j;
        xr += g_Xr[idx];
        xi += g_Xi[idx];
    }
    xr *=  (1.f/(float)NN);
    xi *= -(1.f/(float)NN);
    float g = g_gate[b*MM+m];
    float wrv = wr[c*MM+m], wiv = wi[c*MM+m];
    g_Yr[o] =  g*(xr*wrv - xi*wiv);
    g_Yi[o] = -g*(xr*wiv + xi*wrv);    // pre-negated for synthesis fma2
}

// ---------------- kernel 3: synthesis (f32x2 GEMM, conflict-free smem) ----------------
__global__ void __launch_bounds__(256) k_synth(const float* __restrict__ z,
                                               const float* __restrict__ bias,
                                               float* __restrict__ out)
{
    int nt = blockIdx.x, b = blockIdx.y;
    int n0 = nt*128;
    __shared__ float zs[128], zp[128];
    __shared__ float kk[MP], cc2[MP], ii[MP];
    __shared__ __align__(16) float cw[16][128], sw[16][128];
    __shared__ ull_t y2r[16][65], y2i[16][65];

    int tid = threadIdx.x;
    if (tid < 128){
        float zv = z[b*NN + n0 + tid];
        zs[tid] = zv;
        zp[tid] = zv*(1.f/PI_F);
    }
    for (int j = tid; j < MP; j += 256){ kk[j]=g_kcpt[j]; cc2[j]=g_ccpt[j]; ii[j]=g_iwcpt[j]; }

    int w = tid >> 5, l = tid & 31;
    int cb = w*8, n4 = l*4;
    ull_t accp[8][2];
    #pragma unroll
    for (int c=0;c<8;c++){ accp[c][0]=0ull; accp[c][1]=0ull; }

    int Mact = g_Mact;
    int T = (Mact + 15) >> 4;
    int cl = tid >> 2, ql = tid & 3;
    size_t ybase = ((size_t)b*CC + cl)*MP;

    for (int t=0;t<T;t++){
        int j0 = t*16;
        __syncthreads();
        {
            float4 vr = *(const float4*)&g_Yr[ybase + j0 + ql*4];
            float4 vi = *(const float4*)&g_Yi[ybase + j0 + ql*4];
            y2r[ql*4+0][cl]=f2dup(vr.x); y2r[ql*4+1][cl]=f2dup(vr.y);
            y2r[ql*4+2][cl]=f2dup(vr.z); y2r[ql*4+3][cl]=f2dup(vr.w);
            y2i[ql*4+0][cl]=f2dup(vi.x); y2i[ql*4+1][cl]=f2dup(vi.y);
            y2i[ql*4+2][cl]=f2dup(vi.z); y2i[ql*4+3][cl]=f2dup(vi.w);
        }
        #pragma unroll
        for (int e=0;e<8;e++){
            int idx = e*256 + tid;
            int jj = idx >> 7, nb = idx & 127;
            float s,c; __sincosf(zs[nb]*kk[j0+jj], &s, &c);
            float d = (zp[nb]-cc2[j0+jj])*ii[j0+jj];
            float wgt = __expf(-0.5f*d*d);
            cw[jj][nb] = c*wgt;
            sw[jj][nb] = s*wgt;
        }
        __syncthreads();
        #pragma unroll 2
        for (int jj=0;jj<16;jj++){
            ulonglong2 cp = *(const ulonglong2*)&cw[jj][n4];
            ulonglong2 sp = *(const ulonglong2*)&sw[jj][n4];
            #pragma unroll
            for (int c=0;c<8;c++){
                ull_t yr = y2r[jj][cb+c];
                ull_t yi = y2i[jj][cb+c];
                accp[c][0] = f2fma(yr, cp.x, f2fma(yi, sp.x, accp[c][0]));
                accp[c][1] = f2fma(yr, cp.y, f2fma(yi, sp.y, accp[c][1]));
            }
        }
    }

    #pragma unroll
    for (int c=0;c<8;c++){
        int cc_ = cb + c;
        float bv = bias[cc_];
        float2 p0 = f2unpack(accp[c][0]), p1 = f2unpack(accp[c][1]);
        float4 o; o.x=p0.x+bv; o.y=p0.y+bv; o.z=p1.x+bv; o.w=p1.y+bv;
        *(float4*)(out + ((size_t)(b*CC + cc_))*NN + n0 + n4) = o;
    }
}

// ---------------- launch ----------------
extern "C" void kernel_launch(void* const* d_in, const int* in_sizes, int n_in,
                              void* d_out, int out_size)
{
    const float* x_feat          = (const float*)d_in[0];
    const float* z               = (const float*)d_in[1];
    const float* temb            = (const float*)d_in[2];
    const float* kappa_raw       = (const float*)d_in[3];
    const float* gabor_c         = (const float*)d_in[4];
    const float* gabor_omega_raw = (const float*)d_in[5];
    const float* wr              = (const float*)d_in[6];
    const float* wi              = (const float*)d_in[7];
    const float* bias            = (const float*)d_in[8];
    const float* tproj_w         = (const float*)d_in[9];
    const float* tproj_b         = (const float*)d_in[10];
    const float* mlp_w1          = (const float*)d_in[11];
    const float* mlp_b1          = (const float*)d_in[12];
    const float* mlp_w2          = (const float*)d_in[13];
    const float* mlp_b2          = (const float*)d_in[14];
    const float* tau0            = (const float*)d_in[15];
    const float* tau1            = (const float*)d_in[16];
    const float* alphar          = (const float*)d_in[17];
    const float* glow            = (const float*)d_in[18];
    const float* gmid            = (const float*)d_in[19];
    const float* ghigh           = (const float*)d_in[20];
    float* out = (float*)d_out;

    k_dummy<<<1, 32>>>();                  // shifts k_analysis into ncu capture slot
    k_batch<<<BB, 256>>>(temb, tproj_w, tproj_b, mlp_w1, mlp_b1, mlp_w2, mlp_b2, tau0, tau1);
    k_kappa<<<1, 256>>>(kappa_raw, gabor_c, gabor_omega_raw, alphar, glow, gmid, ghigh);
    dim3 g1((MM + 63)/64, NSPLIT, BB);     // (5, 16, 16); inactive m-tiles early-exit
    k_analysis<<<g1, 256>>>(x_feat, z);
    k_comb<<<BB*CC, MP>>>(wr, wi);
    dim3 g2(NN/128, BB);                   // (32, 16)
    k_synth<<<g2, 256>>>(z, bias, out);
}